// round 17
// baseline (speedup 1.0000x reference)
#include <cuda_runtime.h>
#include <cuda_bf16.h>
#include <mma.h>
#include <cstdint>
#include <math.h>

using namespace nvcuda;

#define B_   128
#define N_   256
#define E_   2048
#define GTOT 256   // q graphs [0,128) + c graphs [128,256)

// ---------------- device scratch (static globals: no allocs) ----------------
__device__ __nv_bfloat16 g_Xhi[GTOT * N_ * 128];   // layer1 out hi (128-d)
__device__ __nv_bfloat16 g_Xlo[GTOT * N_ * 128];
__device__ __nv_bfloat16 g_Phi[GTOT * N_ * 32];    // final emb hi (for pair mm)
__device__ __nv_bfloat16 g_Plo[GTOT * N_ * 32];
__device__ float2   g_edge[GTOT * E_];         // packed (coef, src-as-float-bits)
__device__ int      g_rowptr[GTOT * 257];
__device__ float    g_invdeg[GTOT * N_];
__device__ float    g_pool[GTOT * 32];
__device__ float    g_scoresT[B_ * 16];
__device__ unsigned g_minmax[2];
__device__ int      g_hist[16];
__device__ int      g_done;

// monotone float<->uint mapping for atomicMin/Max over signed floats
__device__ __forceinline__ unsigned encf(float f) {
    unsigned u = __float_as_uint(f);
    return (u & 0x80000000u) ? ~u : (u | 0x80000000u);
}
__device__ __forceinline__ float decf(unsigned u) {
    return (u & 0x80000000u) ? __uint_as_float(u & 0x7fffffffu)
                             : __uint_as_float(~u);
}

// pack 4 floats -> (hi uint2, lo uint2) of bf16
__device__ __forceinline__ void split4(float4 v, uint2& hq, uint2& lq) {
    __nv_bfloat16 h0 = __float2bfloat16(v.x);
    __nv_bfloat16 h1 = __float2bfloat16(v.y);
    __nv_bfloat16 h2 = __float2bfloat16(v.z);
    __nv_bfloat16 h3 = __float2bfloat16(v.w);
    __nv_bfloat16 l0 = __float2bfloat16(v.x - __bfloat162float(h0));
    __nv_bfloat16 l1 = __float2bfloat16(v.y - __bfloat162float(h1));
    __nv_bfloat16 l2 = __float2bfloat16(v.z - __bfloat162float(h2));
    __nv_bfloat16 l3 = __float2bfloat16(v.w - __bfloat162float(h3));
    __nv_bfloat162 ph01(h0, h1), ph23(h2, h3), pl01(l0, l1), pl23(l2, l3);
    hq.x = *(unsigned*)&ph01; hq.y = *(unsigned*)&ph23;
    lq.x = *(unsigned*)&pl01; lq.y = *(unsigned*)&pl23;
}

// ======================= layer 1: inline CSR + stage X/W -> wmma -> agg =======================
// smem: A(139264) | W(69632) | edges(16384) | rowptr(1032+pad) | invdeg(1024)
//       | dinvs(1024) | cnt(1024) | off(1024)
__global__ void __launch_bounds__(512) k_fused1(
    const float* __restrict__ in0, const float* __restrict__ in1,
    const int* __restrict__ eq, const int* __restrict__ ec,
    const float* __restrict__ W1, const float* __restrict__ bias)
{
    constexpr int K = 128, FO = 128;
    constexpr int LDA = K + 8;
    constexpr int LDB = FO + 8;
    extern __shared__ __align__(16) char smc[];
    __nv_bfloat16* Ahi = (__nv_bfloat16*)smc;          // 256*LDA
    __nv_bfloat16* Alo = Ahi + 256 * LDA;
    __nv_bfloat16* Bhi = Alo + 256 * LDA;              // K*LDB
    __nv_bfloat16* Blo = Bhi + K * LDB;
    float2* esm = (float2*)(Blo + K * LDB);            // E_
    int*    rsm = (int*)(esm + E_);                    // 258
    float*  dsm = (float*)(rsm + 258);                 // 256 (invdeg)
    float*  dinvs = dsm + 256;                         // 256 (deg^-1/2)
    int*    cntp  = (int*)(dinvs + 256);               // 256
    int*    offp  = cntp + 256;                        // 256

    const int g = blockIdx.x;
    const int t = threadIdx.x;
    const int wid = t >> 5;

    // ---- inline CSR build ----
    const int* ebase = (g < B_) ? (eq + (size_t)g * 2 * E_)
                                : (ec + (size_t)(g - B_) * 2 * E_);
    const int* src = ebase;
    const int* dst = ebase + E_;

    if (t < 256) cntp[t] = 0;
    __syncthreads();
    for (int e = t; e < E_; e += 512) atomicAdd(&cntp[dst[e]], 1);
    __syncthreads();
    if (t < 256) {
        float deg = (float)cntp[t] + 1.0f;
        dinvs[t] = rsqrtf(deg);
        float id = 1.0f / deg;
        dsm[t] = id;
        g_invdeg[g * N_ + t] = id;
        rsm[t] = cntp[t];
    }
    __syncthreads();
    for (int s = 1; s < 256; s <<= 1) {
        int add = 0;
        if (t < 256 && t >= s) add = rsm[t - s];
        __syncthreads();
        if (t < 256) rsm[t] += add;
        __syncthreads();
    }
    if (t < 256) offp[t] = rsm[t] - cntp[t];   // exclusive
    __syncthreads();
    if (t < 256) rsm[t] = offp[t];
    if (t == 0) rsm[256] = E_;
    __syncthreads();
    for (int i = t; i < 257; i += 512) g_rowptr[g * 257 + i] = rsm[i];
    for (int e = t; e < E_; e += 512) {
        int d = dst[e];
        int s_ = src[e];
        int pos = atomicAdd(&offp[d], 1);
        float2 ed = make_float2(dinvs[s_] * dinvs[d], __int_as_float(s_));
        esm[pos] = ed;
        g_edge[g * E_ + pos] = ed;
    }

    // ---- stage X (fp32 -> hi/lo) and W1 (fp32 -> hi/lo) ----
    {
        const float* X = (g < B_) ? in0 + (size_t)g * N_ * K
                                  : in1 + (size_t)(g - B_) * N_ * K;
        const float4* X4 = (const float4*)X;
        constexpr int KQ = K / 4;
        for (int i = t; i < N_ * KQ; i += 512) {
            int r = i / KQ, c = i % KQ;
            uint2 hq, lq;
            split4(X4[i], hq, lq);
            ((uint2*)(Ahi + r * LDA))[c] = hq;
            ((uint2*)(Alo + r * LDA))[c] = lq;
        }
    }
    {
        const float4* W4 = (const float4*)W1;
        constexpr int FQ = FO / 4;
        for (int i = t; i < K * FQ; i += 512) {
            int r = i / FQ, c = i % FQ;
            uint2 hq, lq;
            split4(W4[i], hq, lq);
            ((uint2*)(Bhi + r * LDB))[c] = hq;
            ((uint2*)(Blo + r * LDB))[c] = lq;
        }
    }
    __syncthreads();

    constexpr int NT = FO / 16;
    wmma::fragment<wmma::accumulator, 16, 16, 16, float> C[NT];
#pragma unroll
    for (int n = 0; n < NT; n++) wmma::fill_fragment(C[n], 0.0f);

    const __nv_bfloat16* Ah = Ahi + (size_t)(wid * 16) * LDA;
    const __nv_bfloat16* Al = Alo + (size_t)(wid * 16) * LDA;
#pragma unroll
    for (int k0 = 0; k0 < K; k0 += 16) {
        wmma::fragment<wmma::matrix_a, 16, 16, 16, __nv_bfloat16, wmma::row_major> ah, al;
        wmma::load_matrix_sync(ah, Ah + k0, LDA);
        wmma::load_matrix_sync(al, Al + k0, LDA);
#pragma unroll
        for (int n = 0; n < NT; n++) {
            wmma::fragment<wmma::matrix_b, 16, 16, 16, __nv_bfloat16, wmma::row_major> bh, bl;
            wmma::load_matrix_sync(bh, Bhi + (size_t)k0 * LDB + n * 16, LDB);
            wmma::load_matrix_sync(bl, Blo + (size_t)k0 * LDB + n * 16, LDB);
            wmma::mma_sync(C[n], ah, bh, C[n]);
            wmma::mma_sync(C[n], ah, bl, C[n]);
            wmma::mma_sync(C[n], al, bh, C[n]);
        }
    }
    __syncthreads();

    float* Hs = (float*)smc;
#pragma unroll
    for (int n = 0; n < NT; n++)
        wmma::store_matrix_sync(Hs + (size_t)(wid * 16) * FO + n * 16, C[n],
                                FO, wmma::mem_row_major);
    __syncthreads();

    constexpr int QPN = FO / 4;
    constexpr int NPB = 512 / QPN;
    const int fq = t % QPN;
    const int n0 = t / QPN;
    const float4 bf = ((const float4*)bias)[fq];
    const float4* h4 = (const float4*)Hs;
    uint2* OHI = (uint2*)g_Xhi + (size_t)g * N_ * QPN;
    uint2* OLO = (uint2*)g_Xlo + (size_t)g * N_ * QPN;

    for (int n = n0; n < N_; n += NPB) {
        const int e0 = rsm[n], e1 = rsm[n + 1];
        float4 a0 = make_float4(0.f, 0.f, 0.f, 0.f);
        float4 a1 = make_float4(0.f, 0.f, 0.f, 0.f);
        int e = e0;
        for (; e + 1 < e1; e += 2) {
            float2 ed0 = esm[e];
            float2 ed1 = esm[e + 1];
            float4 h0 = h4[__float_as_int(ed0.y) * QPN + fq];
            float4 h1 = h4[__float_as_int(ed1.y) * QPN + fq];
            a0.x += h0.x * ed0.x; a0.y += h0.y * ed0.x;
            a0.z += h0.z * ed0.x; a0.w += h0.w * ed0.x;
            a1.x += h1.x * ed1.x; a1.y += h1.y * ed1.x;
            a1.z += h1.z * ed1.x; a1.w += h1.w * ed1.x;
        }
        if (e < e1) {
            float2 ed0 = esm[e];
            float4 h0 = h4[__float_as_int(ed0.y) * QPN + fq];
            a0.x += h0.x * ed0.x; a0.y += h0.y * ed0.x;
            a0.z += h0.z * ed0.x; a0.w += h0.w * ed0.x;
        }
        const float id = dsm[n];
        float4 hs = h4[n * QPN + fq];
        float4 v;
        v.x = fmaxf(a0.x + a1.x + hs.x * id + bf.x, 0.f);
        v.y = fmaxf(a0.y + a1.y + hs.y * id + bf.y, 0.f);
        v.z = fmaxf(a0.z + a1.z + hs.z * id + bf.z, 0.f);
        v.w = fmaxf(a0.w + a1.w + hs.w * id + bf.w, 0.f);
        uint2 hq, lq;
        split4(v, hq, lq);
        OHI[n * QPN + fq] = hq;
        OLO[n * QPN + fq] = lq;
    }
}

// ======================= layers 2+3 + attention pooling, fully smem-resident =======================
__global__ void __launch_bounds__(512) k_fused23(
    const float* __restrict__ W2f, const float* __restrict__ W3f,
    const float* __restrict__ b2, const float* __restrict__ b3,
    const float* __restrict__ Watt)
{
    constexpr int LDA2 = 136, LDB2 = 72, LDA3 = 72, LDB3 = 40;
    extern __shared__ __align__(16) char smc[];
    __nv_bfloat16* A2hi = (__nv_bfloat16*)smc;
    __nv_bfloat16* A2lo = A2hi + 256 * LDA2;
    __nv_bfloat16* W2hi = (__nv_bfloat16*)(smc + 139264);
    __nv_bfloat16* W2lo = W2hi + 128 * LDB2;
    __nv_bfloat16* W3hi = W2lo + 128 * LDB2;
    __nv_bfloat16* W3lo = W3hi + 64 * LDB3;
    float2* esm = (float2*)(smc + 186368);
    int*    rsm = (int*)(smc + 202752);
    float*  dsm = (float*)(smc + 203784);
    float*  part   = (float*)(smc + 204808);   // 512 floats
    float*  colsum = part + 512;
    float*  ctx    = colsum + 32;
    float*  score  = ctx + 32;

    float* H2  = (float*)smc;                          // [0, 64K)
    __nv_bfloat16* A3hi = (__nv_bfloat16*)(smc + 65536);
    __nv_bfloat16* A3lo = A3hi + 256 * LDA3;
    float* H3  = (float*)smc;                          // [0, 32K)
    float* Es  = (float*)(smc + 32768);                // emb fp32 [32K, 64K)

    const int g = blockIdx.x;
    const int t = threadIdx.x;
    const int wid = t >> 5;

    // block 0 initializes pair-phase globals (consumed only after this kernel)
    if (g == 0) {
        if (t == 0) { g_minmax[0] = 0xffffffffu; g_minmax[1] = 0u; g_done = 0; }
        if (t < 16) g_hist[t] = 0;
    }

    // ---- stage A2 (from layer1 output), W2/W3 (fp32 -> hi/lo), edges ----
    {
        const uint4* GH = (const uint4*)(g_Xhi + (size_t)g * N_ * 128);
        const uint4* GL = (const uint4*)(g_Xlo + (size_t)g * N_ * 128);
        for (int i = t; i < N_ * 16; i += 512) {
            int r = i / 16, c = i % 16;
            ((uint4*)(A2hi + r * LDA2))[c] = GH[i];
            ((uint4*)(A2lo + r * LDA2))[c] = GL[i];
        }
    }
    {
        const float4* W4 = (const float4*)W2f;   // 128x64 -> 2048 float4
        for (int i = t; i < 128 * 16; i += 512) {
            int r = i / 16, c = i % 16;
            uint2 hq, lq;
            split4(W4[i], hq, lq);
            ((uint2*)(W2hi + r * LDB2))[c] = hq;
            ((uint2*)(W2lo + r * LDB2))[c] = lq;
        }
        const float4* W34 = (const float4*)W3f;  // 64x32 -> 512 float4
        for (int i = t; i < 64 * 8; i += 512) {
            int r = i / 8, c = i % 8;
            uint2 hq, lq;
            split4(W34[i], hq, lq);
            ((uint2*)(W3hi + r * LDB3))[c] = hq;
            ((uint2*)(W3lo + r * LDB3))[c] = lq;
        }
    }
    for (int i = t; i < E_; i += 512) esm[i] = g_edge[(size_t)g * E_ + i];
    for (int i = t; i < 257; i += 512) rsm[i] = g_rowptr[g * 257 + i];
    for (int i = t; i < 256; i += 512) dsm[i] = g_invdeg[g * N_ + i];
    __syncthreads();

    // ======== layer 2 GEMM (FO=64, NT=4) ========
    {
        wmma::fragment<wmma::accumulator, 16, 16, 16, float> C[4];
#pragma unroll
        for (int n = 0; n < 4; n++) wmma::fill_fragment(C[n], 0.0f);
        const __nv_bfloat16* Ah = A2hi + (size_t)(wid * 16) * LDA2;
        const __nv_bfloat16* Al = A2lo + (size_t)(wid * 16) * LDA2;
#pragma unroll
        for (int k0 = 0; k0 < 128; k0 += 16) {
            wmma::fragment<wmma::matrix_a, 16, 16, 16, __nv_bfloat16, wmma::row_major> ah, al;
            wmma::load_matrix_sync(ah, Ah + k0, LDA2);
            wmma::load_matrix_sync(al, Al + k0, LDA2);
#pragma unroll
            for (int n = 0; n < 4; n++) {
                wmma::fragment<wmma::matrix_b, 16, 16, 16, __nv_bfloat16, wmma::row_major> bh, bl;
                wmma::load_matrix_sync(bh, W2hi + (size_t)k0 * LDB2 + n * 16, LDB2);
                wmma::load_matrix_sync(bl, W2lo + (size_t)k0 * LDB2 + n * 16, LDB2);
                wmma::mma_sync(C[n], ah, bh, C[n]);
                wmma::mma_sync(C[n], ah, bl, C[n]);
                wmma::mma_sync(C[n], al, bh, C[n]);
            }
        }
        __syncthreads();
#pragma unroll
        for (int n = 0; n < 4; n++)
            wmma::store_matrix_sync(H2 + (size_t)(wid * 16) * 64 + n * 16, C[n],
                                    64, wmma::mem_row_major);
        __syncthreads();
    }

    // ======== layer 2 aggregate ========
    {
        constexpr int QPN = 16;
        constexpr int NPB = 32;
        const int fq = t % QPN;
        const int n0 = t / QPN;
        const float4 bf = ((const float4*)b2)[fq];
        const float4* h4 = (const float4*)H2;
        for (int n = n0; n < N_; n += NPB) {
            const int e0 = rsm[n], e1 = rsm[n + 1];
            float4 a0 = make_float4(0.f, 0.f, 0.f, 0.f);
            float4 a1 = make_float4(0.f, 0.f, 0.f, 0.f);
            int e = e0;
            for (; e + 1 < e1; e += 2) {
                float2 ed0 = esm[e];
                float2 ed1 = esm[e + 1];
                float4 h0 = h4[__float_as_int(ed0.y) * QPN + fq];
                float4 h1 = h4[__float_as_int(ed1.y) * QPN + fq];
                a0.x += h0.x * ed0.x; a0.y += h0.y * ed0.x;
                a0.z += h0.z * ed0.x; a0.w += h0.w * ed0.x;
                a1.x += h1.x * ed1.x; a1.y += h1.y * ed1.x;
                a1.z += h1.z * ed1.x; a1.w += h1.w * ed1.x;
            }
            if (e < e1) {
                float2 ed0 = esm[e];
                float4 h0 = h4[__float_as_int(ed0.y) * QPN + fq];
                a0.x += h0.x * ed0.x; a0.y += h0.y * ed0.x;
                a0.z += h0.z * ed0.x; a0.w += h0.w * ed0.x;
            }
            const float id = dsm[n];
            float4 hs = h4[n * QPN + fq];
            float4 v;
            v.x = fmaxf(a0.x + a1.x + hs.x * id + bf.x, 0.f);
            v.y = fmaxf(a0.y + a1.y + hs.y * id + bf.y, 0.f);
            v.z = fmaxf(a0.z + a1.z + hs.z * id + bf.z, 0.f);
            v.w = fmaxf(a0.w + a1.w + hs.w * id + bf.w, 0.f);
            uint2 hq, lq;
            split4(v, hq, lq);
            ((uint2*)(A3hi + n * LDA3))[fq] = hq;
            ((uint2*)(A3lo + n * LDA3))[fq] = lq;
        }
        __syncthreads();
    }

    // ======== layer 3 GEMM (K=64, FO=32, NT=2) ========
    {
        wmma::fragment<wmma::accumulator, 16, 16, 16, float> C[2];
#pragma unroll
        for (int n = 0; n < 2; n++) wmma::fill_fragment(C[n], 0.0f);
        const __nv_bfloat16* Ah = A3hi + (size_t)(wid * 16) * LDA3;
        const __nv_bfloat16* Al = A3lo + (size_t)(wid * 16) * LDA3;
#pragma unroll
        for (int k0 = 0; k0 < 64; k0 += 16) {
            wmma::fragment<wmma::matrix_a, 16, 16, 16, __nv_bfloat16, wmma::row_major> ah, al;
            wmma::load_matrix_sync(ah, Ah + k0, LDA3);
            wmma::load_matrix_sync(al, Al + k0, LDA3);
#pragma unroll
            for (int n = 0; n < 2; n++) {
                wmma::fragment<wmma::matrix_b, 16, 16, 16, __nv_bfloat16, wmma::row_major> bh, bl;
                wmma::load_matrix_sync(bh, W3hi + (size_t)k0 * LDB3 + n * 16, LDB3);
                wmma::load_matrix_sync(bl, W3lo + (size_t)k0 * LDB3 + n * 16, LDB3);
                wmma::mma_sync(C[n], ah, bh, C[n]);
                wmma::mma_sync(C[n], ah, bl, C[n]);
                wmma::mma_sync(C[n], al, bh, C[n]);
            }
        }
        __syncthreads();
#pragma unroll
        for (int n = 0; n < 2; n++)
            wmma::store_matrix_sync(H3 + (size_t)(wid * 16) * 32 + n * 16, C[n],
                                    32, wmma::mem_row_major);
        __syncthreads();
    }

    // ======== layer 3 aggregate -> Es (smem) + Phi/Plo (global) ========
    {
        constexpr int QPN = 8;
        constexpr int NPB = 64;
        const int fq = t % QPN;
        const int n0 = t / QPN;
        const float4 bf = ((const float4*)b3)[fq];
        const float4* h4 = (const float4*)H3;
        uint2* PHI = (uint2*)g_Phi + (size_t)g * N_ * QPN;
        uint2* PLO = (uint2*)g_Plo + (size_t)g * N_ * QPN;
        for (int n = n0; n < N_; n += NPB) {
            const int e0 = rsm[n], e1 = rsm[n + 1];
            float4 a0 = make_float4(0.f, 0.f, 0.f, 0.f);
            float4 a1 = make_float4(0.f, 0.f, 0.f, 0.f);
            int e = e0;
            for (; e + 1 < e1; e += 2) {
                float2 ed0 = esm[e];
                float2 ed1 = esm[e + 1];
                float4 h0 = h4[__float_as_int(ed0.y) * QPN + fq];
                float4 h1 = h4[__float_as_int(ed1.y) * QPN + fq];
                a0.x += h0.x * ed0.x; a0.y += h0.y * ed0.x;
                a0.z += h0.z * ed0.x; a0.w += h0.w * ed0.x;
                a1.x += h1.x * ed1.x; a1.y += h1.y * ed1.x;
                a1.z += h1.z * ed1.x; a1.w += h1.w * ed1.x;
            }
            if (e < e1) {
                float2 ed0 = esm[e];
                float4 h0 = h4[__float_as_int(ed0.y) * QPN + fq];
                a0.x += h0.x * ed0.x; a0.y += h0.y * ed0.x;
                a0.z += h0.z * ed0.x; a0.w += h0.w * ed0.x;
            }
            const float id = dsm[n];
            float4 hs = h4[n * QPN + fq];
            float4 v;
            v.x = a0.x + a1.x + hs.x * id + bf.x;
            v.y = a0.y + a1.y + hs.y * id + bf.y;
            v.z = a0.z + a1.z + hs.z * id + bf.z;
            v.w = a0.w + a1.w + hs.w * id + bf.w;
            ((float4*)Es)[n * QPN + fq] = v;
            uint2 hq, lq;
            split4(v, hq, lq);
            PHI[n * QPN + fq] = hq;
            PLO[n * QPN + fq] = lq;
        }
        __syncthreads();
    }

    // ======== attention pooling (parallel two-stage reductions) ========
    {
        const int f = t & 31, grp = t >> 5;
        float s = 0.f;
        for (int n = grp * 16; n < grp * 16 + 16; n++) s += Es[n * 32 + f];
        part[grp * 32 + f] = s;
    }
    __syncthreads();
    if (t < 32) {
        float s = 0.f;
#pragma unroll
        for (int p = 0; p < 16; p++) s += part[p * 32 + t];
        colsum[t] = s;
    }
    __syncthreads();
    if (t < 32) {
        float a = 0.f;
        for (int i = 0; i < 32; i++) a += colsum[i] * Watt[t * 32 + i];
        ctx[t] = tanhf(a * (1.0f / 256.0f));
    }
    __syncthreads();
    if (t < 256) {
        const int lane = t & 31;
        float d = 0.f;
#pragma unroll
        for (int j = 0; j < 32; j++) {
            int i = (lane + j) & 31;
            d += Es[t * 32 + i] * ctx[i];
        }
        score[t] = 1.0f / (1.0f + expf(-d));
    }
    __syncthreads();
    {
        const int f = t & 31, grp = t >> 5;
        float s = 0.f;
        for (int n = grp * 16; n < grp * 16 + 16; n++) s += Es[n * 32 + f] * score[n];
        part[grp * 32 + f] = s;
    }
    __syncthreads();
    if (t < 32) {
        float s = 0.f;
#pragma unroll
        for (int p = 0; p < 16; p++) s += part[p * 32 + t];
        g_pool[g * 32 + t] = s;
    }
}

// ============ pair matrix: shared staging + split-bf16 wmma tile compute ============
template<typename F>
__device__ __forceinline__ void pair_tiles(int half, int b, int t, F&& consume) {
    constexpr int LD = 40;
    __shared__ __align__(16) __nv_bfloat16 Qh[128 * LD];
    __shared__ __align__(16) __nv_bfloat16 Ql[128 * LD];
    __shared__ __align__(16) __nv_bfloat16 Ch[256 * LD];
    __shared__ __align__(16) __nv_bfloat16 Cl[256 * LD];

    const int wid = t >> 5;

    {
        const uint4* QH = (const uint4*)(g_Phi + ((size_t)b * N_ + half * 128) * 32);
        const uint4* QL = (const uint4*)(g_Plo + ((size_t)b * N_ + half * 128) * 32);
        for (int i = t; i < 128 * 4; i += 256) {
            int r = i / 4, c = i % 4;
            ((uint4*)(Qh + r * LD))[c] = QH[i];
            ((uint4*)(Ql + r * LD))[c] = QL[i];
        }
        const uint4* CH = (const uint4*)(g_Phi + (size_t)(B_ + b) * N_ * 32);
        const uint4* CL = (const uint4*)(g_Plo + (size_t)(B_ + b) * N_ * 32);
        for (int i = t; i < 256 * 4; i += 256) {
            int r = i / 4, c = i % 4;
            ((uint4*)(Ch + r * LD))[c] = CH[i];
            ((uint4*)(Cl + r * LD))[c] = CL[i];
        }
    }
    __syncthreads();

    wmma::fragment<wmma::matrix_a, 16, 16, 16, __nv_bfloat16, wmma::row_major> ah[2], al[2];
#pragma unroll
    for (int kt = 0; kt < 2; kt++) {
        wmma::load_matrix_sync(ah[kt], Qh + (size_t)(wid * 16) * LD + kt * 16, LD);
        wmma::load_matrix_sync(al[kt], Ql + (size_t)(wid * 16) * LD + kt * 16, LD);
    }

#pragma unroll
    for (int ct = 0; ct < 16; ct++) {
        wmma::fragment<wmma::accumulator, 16, 16, 16, float> acc;
        wmma::fill_fragment(acc, 0.0f);
#pragma unroll
        for (int kt = 0; kt < 2; kt++) {
            wmma::fragment<wmma::matrix_b, 16, 16, 16, __nv_bfloat16, wmma::col_major> bh, bl;
            wmma::load_matrix_sync(bh, Ch + (size_t)(ct * 16) * LD + kt * 16, LD);
            wmma::load_matrix_sync(bl, Cl + (size_t)(ct * 16) * LD + kt * 16, LD);
            wmma::mma_sync(acc, ah[kt], bh, acc);
            wmma::mma_sync(acc, ah[kt], bl, acc);
            wmma::mma_sync(acc, al[kt], bh, acc);
        }
        consume(acc);
    }
}

// ---- pass 1: global min/max (x<2) + NTN folded in (x==2) ----
__global__ void __launch_bounds__(256) k_pair_minmax(
    const float* __restrict__ ntnW, const float* __restrict__ ntnV,
    const float* __restrict__ ntnb) {
    const int t = threadIdx.x, wid = t >> 5, lane = t & 31;
    const int b = blockIdx.y;

    if (blockIdx.x == 2) {
        __shared__ float e1[32], e2[32];
        if (t < 32)      e1[t]      = g_pool[b * 32 + t];
        else if (t < 64) e2[t - 32] = g_pool[(B_ + b) * 32 + (t - 32)];
        __syncthreads();
#pragma unroll
        for (int nn = wid; nn < 16; nn += 8) {
            const float4* Wt = (const float4*)(ntnW + nn * 1024 + lane * 32);
            float a = 0.f;
#pragma unroll
            for (int j = 0; j < 8; j++) {
                float4 wv = Wt[j];
                a += wv.x * e2[j * 4] + wv.y * e2[j * 4 + 1]
                   + wv.z * e2[j * 4 + 2] + wv.w * e2[j * 4 + 3];
            }
            float partial = e1[lane] * a
                          + e1[lane] * ntnV[nn * 64 + lane]
                          + e2[lane] * ntnV[nn * 64 + 32 + lane];
#pragma unroll
            for (int o = 16; o; o >>= 1)
                partial += __shfl_xor_sync(0xffffffffu, partial, o);
            if (lane == 0)
                g_scoresT[b * 16 + nn] = fmaxf(partial + ntnb[nn], 0.f);
        }
        return;
    }

    __shared__ float wmn[8], wmx[8];
    const int half = blockIdx.x;

    float vmin = 3.402823466e38f, vmax = -3.402823466e38f;
    pair_tiles(half, b, t,
        [&](wmma::fragment<wmma::accumulator, 16, 16, 16, float>& acc) {
#pragma unroll
            for (int i = 0; i < acc.num_elements; i++) {
                vmin = fminf(vmin, acc.x[i]);
                vmax = fmaxf(vmax, acc.x[i]);
            }
        });

#pragma unroll
    for (int o = 16; o; o >>= 1) {
        vmin = fminf(vmin, __shfl_xor_sync(0xffffffffu, vmin, o));
        vmax = fmaxf(vmax, __shfl_xor_sync(0xffffffffu, vmax, o));
    }
    if (lane == 0) { wmn[wid] = vmin; wmx[wid] = vmax; }
    __syncthreads();
    if (t == 0) {
        float m = wmn[0], M = wmx[0];
        for (int i = 1; i < 8; i++) { m = fminf(m, wmn[i]); M = fmaxf(M, wmx[i]); }
        atomicMin(&g_minmax[0], encf(m));
        atomicMax(&g_minmax[1], encf(M));
    }
}

// ---- pass 2: recompute identical tiles, histogram; last block runs MLP head ----
__global__ void __launch_bounds__(256) k_pair_hist(
    const float* __restrict__ fc1W, const float* __restrict__ fc1b,
    const float* __restrict__ fc2W, const float* __restrict__ fc2b,
    float* __restrict__ out) {
    __shared__ int hsm[8][16];
    __shared__ int islast;
    const int half = blockIdx.x, b = blockIdx.y;
    const int t = threadIdx.x, wid = t >> 5;

    if ((t & 31) < 16) hsm[wid][t & 15] = 0;
    __syncthreads();

    const float lo = decf(g_minmax[0]);
    const float inv = 16.0f / (decf(g_minmax[1]) - lo);
    int* myh = hsm[wid];

    pair_tiles(half, b, t,
        [&](wmma::fragment<wmma::accumulator, 16, 16, 16, float>& acc) {
#pragma unroll
            for (int i = 0; i < acc.num_elements; i++) {
                int bi = (int)floorf((acc.x[i] - lo) * inv);
                bi = bi < 0 ? 0 : (bi > 15 ? 15 : bi);
                atomicAdd(&myh[bi], 1);
            }
        });

    __syncthreads();
    if (t < 16) {
        int s = 0;
#pragma unroll
        for (int w = 0; w < 8; w++) s += hsm[w][t];
        atomicAdd(&g_hist[t], s);
    }
    __threadfence();
    __syncthreads();
    if (t == 0) {
        int old = atomicAdd(&g_done, 1);
        islast = (old == 2 * B_ - 1);
    }
    __syncthreads();
    if (!islast) return;

    // ---- final MLP head (last block only) ----
    __shared__ float h[16];
    if (t < 16) h[t] = (float)g_hist[t] * (1.0f / 8388608.0f);
    __syncthreads();
    if (t < B_) {
        float sc[16];
#pragma unroll
        for (int k = 0; k < 16; k++) sc[k] = g_scoresT[t * 16 + k];
        float p = fc2b[0];
#pragma unroll
        for (int j = 0; j < 16; j++) {
            float a = fc1b[j];
#pragma unroll
            for (int k = 0; k < 16; k++) a += sc[k] * fc1W[j * 32 + k];
#pragma unroll
            for (int k = 0; k < 16; k++) a += h[k] * fc1W[j * 32 + 16 + k];
            p += fmaxf(a, 0.f) * fc2W[j];
        }
        out[t] = 1.0f / (1.0f + expf(-p));
    }
}

// ---------------- launch ----------------
extern "C" void kernel_launch(void* const* d_in, const int* in_sizes, int n_in,
                              void* d_out, int out_size) {
    const float* xq   = (const float*)d_in[0];
    const float* xc   = (const float*)d_in[1];
    const int*   eq   = (const int*)d_in[2];
    const int*   ec   = (const int*)d_in[3];
    const float* W1   = (const float*)d_in[4];
    const float* b1   = (const float*)d_in[5];
    const float* W2   = (const float*)d_in[6];
    const float* b2   = (const float*)d_in[7];
    const float* W3   = (const float*)d_in[8];
    const float* b3   = (const float*)d_in[9];
    const float* Watt = (const float*)d_in[10];
    const float* ntnW = (const float*)d_in[11];
    const float* ntnV = (const float*)d_in[12];
    const float* ntnb = (const float*)d_in[13];
    const float* fc1W = (const float*)d_in[14];
    const float* fc1b = (const float*)d_in[15];
    const float* fc2W = (const float*)d_in[16];
    const float* fc2b = (const float*)d_in[17];
    float* out = (float*)d_out;

    constexpr int EDGE = E_ * 8 + 258 * 4 + 256 * 4;                   // 18,440
    constexpr int SMF1 = (2 * 256 * 136 + 2 * 128 * 136) * 2 + EDGE
                       + 256 * 4 * 3;                                  // +dinvs/cnt/off = 230,408
    constexpr int SMF23 = 204808 + 3328;                               // 208,136

    cudaFuncSetAttribute(k_fused1,  cudaFuncAttributeMaxDynamicSharedMemorySize, SMF1);
    cudaFuncSetAttribute(k_fused23, cudaFuncAttributeMaxDynamicSharedMemorySize, SMF23);

    k_fused1<<<GTOT, 512, SMF1>>>(xq, xc, eq, ec, W1, b1);
    k_fused23<<<GTOT, 512, SMF23>>>(W2, W3, b2, b3, Watt);

    k_pair_minmax<<<dim3(3, B_), 256>>>(ntnW, ntnV, ntnb);
    k_pair_hist<<<dim3(2, B_), 256>>>(fc1W, fc1b, fc2W, fc2b, out);
}